// round 3
// baseline (speedup 1.0000x reference)
#include <cuda_runtime.h>
#include <cuda_bf16.h>
#include <cstdint>

// ============================================================================
// TernaryLinear: out[8192,4096] = x[8192,4096] @ W[4096,4096]^T + bias
//
// Base-PTX path (harness compiles compute_103 PTX: no tcgen05 allowed).
// x -> per-row scale s, int8 hi/lo split: x ~= s*(256*h + l)  (15.9-bit quant)
// W ternary -> exact int8.
// out = s_row * (256*(H@W^T) + (L@W^T)) + bias, int32 accum via mma.sync s8.
//
// R3: de-spill rebuild. 256 thr/CTA (255-reg budget, core ~120 regs -> no
// spill), BM=64 BN=128 BK=128, warp tile 32x32 dual-pass, 4-stage cp.async.
// ============================================================================

#define M_DIM 8192
#define N_DIM 4096
#define K_DIM 4096
#define BM 64
#define BN 128
#define BK 128                     // int8 elems per K tile (128 B/row)
#define NKT (K_DIM / BK)           // 32
#define NSTAGE 4
#define A_HI_OFF 0
#define A_LO_OFF 8192
#define B_OFF    16384
#define STAGE_BYTES 32768          // A_hi 8K + A_lo 8K + B 16K
#define SMEM_TOTAL (NSTAGE * STAGE_BYTES)   // 128 KB

// Static device scratch (sanctioned workaround for no-alloc rule)
__device__ __align__(128) int8_t g_xh8[(size_t)M_DIM * K_DIM];
__device__ __align__(128) int8_t g_xl8[(size_t)M_DIM * K_DIM];
__device__ __align__(128) int8_t g_w8 [(size_t)N_DIM * K_DIM];
__device__ __align__(128) float  g_scale[M_DIM];

// ---------------------------------------------------------------------------
// PTX helpers
// ---------------------------------------------------------------------------
__device__ __forceinline__ uint32_t smem_u32(const void* p) {
    uint32_t a;
    asm("{ .reg .u64 t; cvta.to.shared.u64 t, %1; cvt.u32.u64 %0, t; }"
        : "=r"(a) : "l"(p));
    return a;
}

#define CP16(dst, src) \
    asm volatile("cp.async.cg.shared.global [%0], [%1], 16;" \
                 :: "r"((uint32_t)(dst)), "l"(src) : "memory")
#define CP_COMMIT() asm volatile("cp.async.commit_group;" ::: "memory")
#define CP_WAIT2()  asm volatile("cp.async.wait_group 2;" ::: "memory")

#define LDSM4(r0, r1, r2, r3, addr) \
    asm volatile("ldmatrix.sync.aligned.m8n8.x4.shared.b16 {%0,%1,%2,%3}, [%4];" \
                 : "=r"(r0), "=r"(r1), "=r"(r2), "=r"(r3) : "r"(addr))

__device__ __forceinline__ void mma_s8(int c[4], const uint32_t a[4],
                                       uint32_t b0, uint32_t b1) {
    asm volatile(
        "mma.sync.aligned.m16n8k32.row.col.s32.s8.s8.s32 "
        "{%0,%1,%2,%3}, {%4,%5,%6,%7}, {%8,%9}, {%0,%1,%2,%3};"
        : "+r"(c[0]), "+r"(c[1]), "+r"(c[2]), "+r"(c[3])
        : "r"(a[0]), "r"(a[1]), "r"(a[2]), "r"(a[3]), "r"(b0), "r"(b1));
}

// ---------------------------------------------------------------------------
// Pre-pass 1: per-row quantize x into int8 hi/lo + row scale
// ---------------------------------------------------------------------------
__global__ void __launch_bounds__(256) quant_x_kernel(const float* __restrict__ x) {
    const int row = blockIdx.x;
    const int t = threadIdx.x;
    const float4* xr = reinterpret_cast<const float4*>(x + (size_t)row * K_DIM);

    float4 v[4];
    float amax = 0.f;
#pragma unroll
    for (int p = 0; p < 4; ++p) {
        v[p] = xr[p * 256 + t];
        amax = fmaxf(amax, fmaxf(fmaxf(fabsf(v[p].x), fabsf(v[p].y)),
                                 fmaxf(fabsf(v[p].z), fabsf(v[p].w))));
    }
#pragma unroll
    for (int o = 16; o; o >>= 1)
        amax = fmaxf(amax, __shfl_xor_sync(0xFFFFFFFFu, amax, o));

    __shared__ float smax[8];
    if ((t & 31) == 0) smax[t >> 5] = amax;
    __syncthreads();
    float bmax = fmaxf(fmaxf(fmaxf(smax[0], smax[1]), fmaxf(smax[2], smax[3])),
                       fmaxf(fmaxf(smax[4], smax[5]), fmaxf(smax[6], smax[7])));

    const float inv = (bmax > 0.f) ? (32639.f / bmax) : 0.f;
    if (t == 0) g_scale[row] = (bmax > 0.f) ? (bmax / 32639.f) : 0.f;

    char4* hp = reinterpret_cast<char4*>(g_xh8 + (size_t)row * K_DIM);
    char4* lp = reinterpret_cast<char4*>(g_xl8 + (size_t)row * K_DIM);
#pragma unroll
    for (int p = 0; p < 4; ++p) {
        int q0 = __float2int_rn(v[p].x * inv);
        int q1 = __float2int_rn(v[p].y * inv);
        int q2 = __float2int_rn(v[p].z * inv);
        int q3 = __float2int_rn(v[p].w * inv);
        int h0 = (q0 + 128) >> 8, h1 = (q1 + 128) >> 8;
        int h2 = (q2 + 128) >> 8, h3 = (q3 + 128) >> 8;
        char4 hc = make_char4((char)h0, (char)h1, (char)h2, (char)h3);
        char4 lc = make_char4((char)(q0 - (h0 << 8)), (char)(q1 - (h1 << 8)),
                              (char)(q2 - (h2 << 8)), (char)(q3 - (h3 << 8)));
        hp[p * 256 + t] = hc;
        lp[p * 256 + t] = lc;
    }
}

// ---------------------------------------------------------------------------
// Pre-pass 2: W float{-1,0,1} -> int8 (exact)
// ---------------------------------------------------------------------------
__global__ void __launch_bounds__(256) quant_w_kernel(const float* __restrict__ w) {
    size_t i = (size_t)blockIdx.x * 256 + threadIdx.x;   // float4 index
    float4 v = reinterpret_cast<const float4*>(w)[i];
    char4 c = make_char4((char)__float2int_rn(v.x), (char)__float2int_rn(v.y),
                         (char)__float2int_rn(v.z), (char)__float2int_rn(v.w));
    reinterpret_cast<char4*>(g_w8)[i] = c;
}

// ---------------------------------------------------------------------------
// Main int8 GEMM. CTA 64x128, 256 thr = 8 warps (2m x 4n), warp tile 32x32,
// dual hi/lo pass (64 acc regs). 4-stage cp.async ring.
// Stage: [A_hi 8K][A_lo 8K][B 16K], rows 128 B, SW128-style xor swizzle.
// ---------------------------------------------------------------------------
__global__ void __launch_bounds__(256, 1)
gemm_s8_kernel(const float* __restrict__ bias, float* __restrict__ out) {
    extern __shared__ char smem[];
    const uint32_t sb = smem_u32(smem);
    const int tid = threadIdx.x;
    const int lane = tid & 31;
    const int wid = tid >> 5;
    const int wm = wid >> 2;           // 0..1
    const int wn = wid & 3;            // 0..3
    const int m0 = blockIdx.y * BM;
    const int n0 = blockIdx.x * BN;

    // --- cp.async mapping (8 x 16B chunks per thread = 32 KB/stage) ---
    // A (64 rows x 8 chunks): thread t -> row t>>2, chunks (t&3)*2 + {0,1}
    const int arow = tid >> 2;
    const int acol = (tid & 3) * 2;
    const int8_t* gH = g_xh8 + (size_t)(m0 + arow) * K_DIM + acol * 16;
    const int8_t* gL = g_xl8 + (size_t)(m0 + arow) * K_DIM + acol * 16;
    const uint32_t aBase = (uint32_t)arow * BK;
    const uint32_t asw0 = aBase + (uint32_t)(((acol + 0) ^ (arow & 7)) << 4);
    const uint32_t asw1 = aBase + (uint32_t)(((acol + 1) ^ (arow & 7)) << 4);
    // B (128 rows x 8 chunks): thread t -> row t>>1, chunks (t&1)*4 + {0..3}
    const int brow = tid >> 1;
    const int bcol = (tid & 1) * 4;
    const int8_t* gW = g_w8 + (size_t)(n0 + brow) * K_DIM + bcol * 16;
    const uint32_t bBase = B_OFF + (uint32_t)brow * BK;
    uint32_t bsw[4];
#pragma unroll
    for (int j = 0; j < 4; ++j)
        bsw[j] = bBase + (uint32_t)(((bcol + j) ^ (brow & 7)) << 4);

#define PREFETCH(it) do {                                                     \
    const int _k = (it) * BK;                                                 \
    const uint32_t _s = sb + (uint32_t)((it) & (NSTAGE - 1)) * STAGE_BYTES;   \
    CP16(_s + A_HI_OFF + asw0, gH + _k);                                      \
    CP16(_s + A_HI_OFF + asw1, gH + _k + 16);                                 \
    CP16(_s + A_LO_OFF + asw0, gL + _k);                                      \
    CP16(_s + A_LO_OFF + asw1, gL + _k + 16);                                 \
    CP16(_s + bsw[0], gW + _k);                                               \
    CP16(_s + bsw[1], gW + _k + 16);                                          \
    CP16(_s + bsw[2], gW + _k + 32);                                          \
    CP16(_s + bsw[3], gW + _k + 48);                                          \
} while (0)

    // --- ldmatrix lane addressing ---
    const int ag = lane >> 3;                                  // 0..3
    const int aRow0 = wm * 32 + ((ag & 1) << 3) + (lane & 7);  // mt=0 A row
    const int agc = ag >> 1;                                   // k-chunk half
    const int bRow = wn * 32 + lane;
    const uint32_t bRowOff = B_OFF + (uint32_t)bRow * BK;
    const int bRowSw = bRow & 7;

    int accH[2][4][4], accL[2][4][4];
#pragma unroll
    for (int mt = 0; mt < 2; ++mt)
#pragma unroll
        for (int nt = 0; nt < 4; ++nt)
#pragma unroll
            for (int i = 0; i < 4; ++i) { accH[mt][nt][i] = 0; accL[mt][nt][i] = 0; }

    // --- prologue: fill 3 stages ---
    PREFETCH(0); CP_COMMIT();
    PREFETCH(1); CP_COMMIT();
    PREFETCH(2); CP_COMMIT();

    for (int it = 0; it < NKT; ++it) {
        CP_WAIT2();            // stage `it` resident (2 groups still in flight)
        __syncthreads();       // all threads' groups for stage `it` visible;
                               // also: compute(it-1) done before overwrite below
        if (it + 3 < NKT) { PREFETCH(it + 3); }
        CP_COMMIT();

        const uint32_t S = sb + (uint32_t)(it & (NSTAGE - 1)) * STAGE_BYTES;
#pragma unroll
        for (int ks = 0; ks < 4; ++ks) {
            uint32_t b0[4], b1[4];
            {
                uint32_t a0 = S + bRowOff + (uint32_t)(((ks * 2)     ^ bRowSw) << 4);
                uint32_t a1 = S + bRowOff + (uint32_t)(((ks * 2 + 1) ^ bRowSw) << 4);
                LDSM4(b0[0], b0[1], b0[2], b0[3], a0);
                LDSM4(b1[0], b1[1], b1[2], b1[3], a1);
            }
            uint32_t ah[2][4], al[2][4];
#pragma unroll
            for (int mt = 0; mt < 2; ++mt) {
                const int rA = aRow0 + mt * 16;
                const int cA = ks * 2 + agc;
                const uint32_t off = (uint32_t)rA * BK +
                                     (uint32_t)((cA ^ (rA & 7)) << 4);
                LDSM4(ah[mt][0], ah[mt][1], ah[mt][2], ah[mt][3], S + A_HI_OFF + off);
                LDSM4(al[mt][0], al[mt][1], al[mt][2], al[mt][3], S + A_LO_OFF + off);
            }
#pragma unroll
            for (int mt = 0; mt < 2; ++mt)
#pragma unroll
                for (int nt = 0; nt < 4; ++nt) {
                    mma_s8(accH[mt][nt], ah[mt], b0[nt], b1[nt]);
                    mma_s8(accL[mt][nt], al[mt], b0[nt], b1[nt]);
                }
        }
        __syncthreads();       // compute(it) done before iter it+1 prefetches
                               // into stage (it+4)&3 == it&3
    }

    // --- epilogue: combine hi/lo, scale, bias, store fp32 ---
#pragma unroll
    for (int mt = 0; mt < 2; ++mt) {
        const int r0 = m0 + wm * 32 + mt * 16 + (lane >> 2);
        const float s0 = g_scale[r0];
        const float s1 = g_scale[r0 + 8];
#pragma unroll
        for (int nt = 0; nt < 4; ++nt) {
            const int col = n0 + wn * 32 + nt * 8 + 2 * (lane & 3);
            const float bv0 = __ldg(bias + col);
            const float bv1 = __ldg(bias + col + 1);
            const int* h = accH[mt][nt];
            const int* l = accL[mt][nt];
            float2 o0, o1;
            o0.x = s0 * (float)(256 * h[0] + l[0]) + bv0;
            o0.y = s0 * (float)(256 * h[1] + l[1]) + bv1;
            o1.x = s1 * (float)(256 * h[2] + l[2]) + bv0;
            o1.y = s1 * (float)(256 * h[3] + l[3]) + bv1;
            *reinterpret_cast<float2*>(out + (size_t)r0 * N_DIM + col) = o0;
            *reinterpret_cast<float2*>(out + (size_t)(r0 + 8) * N_DIM + col) = o1;
        }
    }
#undef PREFETCH
}

// ---------------------------------------------------------------------------
// Launch
// ---------------------------------------------------------------------------
extern "C" void kernel_launch(void* const* d_in, const int* in_sizes, int n_in,
                              void* d_out, int out_size) {
    const float* x    = (const float*)d_in[0];
    const float* w    = (const float*)d_in[1];
    const float* bias = (const float*)d_in[2];
    float* out = (float*)d_out;

    quant_x_kernel<<<M_DIM, 256>>>(x);
    quant_w_kernel<<<(N_DIM * K_DIM / 4) / 256, 256>>>(w);

    cudaFuncSetAttribute(gemm_s8_kernel,
                         cudaFuncAttributeMaxDynamicSharedMemorySize, SMEM_TOTAL);
    dim3 grid(N_DIM / BN, M_DIM / BM);   // (32, 128): n fastest -> W L2-resident
    gemm_s8_kernel<<<grid, 256, SMEM_TOTAL>>>(bias, out);
}

// round 4
// speedup vs baseline: 1.2487x; 1.2487x over previous
#include <cuda_runtime.h>
#include <cuda_bf16.h>
#include <cstdint>

// ============================================================================
// TernaryLinear: out[8192,4096] = x[8192,4096] @ W[4096,4096]^T + bias
//
// R4: dual-pipe hybrid. Legacy mma.sync IMMA on sm_103a measures ~256 int8
// MAC/cyc/SM (rt_SMSP~64) and R2/R3 both sit at that roofline. So:
//   hi pass (x_hi, 8-bit)  -> IMMA tensor pipe (as R3)
//   lo pass (x_lo, 8-bit)  -> dp4a on the fma/alu pipe, concurrently
// out = s_row * (256*(H@W^T) + (L@W^T)) + bias, all-int accumulation (exact).
// Warps 0-3 run hi->lo, warps 4-7 lo->hi so SMSP pairs overlap both pipes.
// ============================================================================

#define M_DIM 8192
#define N_DIM 4096
#define K_DIM 4096
#define BM 64
#define BN 128
#define BK 128                     // int8 elems per K tile (128 B/row)
#define NKT (K_DIM / BK)           // 32
#define NSTAGE 4
#define A_HI_OFF 0
#define A_LO_OFF 8192
#define B_OFF    16384
#define STAGE_BYTES 32768          // A_hi 8K + A_lo 8K + B 16K
#define SMEM_TOTAL (NSTAGE * STAGE_BYTES)   // 128 KB

// Static device scratch (sanctioned workaround for no-alloc rule)
__device__ __align__(128) int8_t g_xh8[(size_t)M_DIM * K_DIM];
__device__ __align__(128) int8_t g_xl8[(size_t)M_DIM * K_DIM];
__device__ __align__(128) int8_t g_w8 [(size_t)N_DIM * K_DIM];
__device__ __align__(128) float  g_scale[M_DIM];

// ---------------------------------------------------------------------------
// PTX helpers
// ---------------------------------------------------------------------------
__device__ __forceinline__ uint32_t smem_u32(const void* p) {
    uint32_t a;
    asm("{ .reg .u64 t; cvta.to.shared.u64 t, %1; cvt.u32.u64 %0, t; }"
        : "=r"(a) : "l"(p));
    return a;
}

#define CP16(dst, src) \
    asm volatile("cp.async.cg.shared.global [%0], [%1], 16;" \
                 :: "r"((uint32_t)(dst)), "l"(src) : "memory")
#define CP_COMMIT() asm volatile("cp.async.commit_group;" ::: "memory")
#define CP_WAIT2()  asm volatile("cp.async.wait_group 2;" ::: "memory")

#define LDSM4(r0, r1, r2, r3, addr) \
    asm volatile("ldmatrix.sync.aligned.m8n8.x4.shared.b16 {%0,%1,%2,%3}, [%4];" \
                 : "=r"(r0), "=r"(r1), "=r"(r2), "=r"(r3) : "r"(addr))

__device__ __forceinline__ void mma_s8(int c[4], const uint32_t a[4],
                                       uint32_t b0, uint32_t b1) {
    asm volatile(
        "mma.sync.aligned.m16n8k32.row.col.s32.s8.s8.s32 "
        "{%0,%1,%2,%3}, {%4,%5,%6,%7}, {%8,%9}, {%0,%1,%2,%3};"
        : "+r"(c[0]), "+r"(c[1]), "+r"(c[2]), "+r"(c[3])
        : "r"(a[0]), "r"(a[1]), "r"(a[2]), "r"(a[3]), "r"(b0), "r"(b1));
}

// ---------------------------------------------------------------------------
// Merged pre-pass: blocks [0,8192) quantize x rows; [8192, 24576) convert W.
// ---------------------------------------------------------------------------
__global__ void __launch_bounds__(256) quant_all_kernel(const float* __restrict__ x,
                                                        const float* __restrict__ w) {
    const int t = threadIdx.x;
    if (blockIdx.x < M_DIM) {
        const int row = blockIdx.x;
        const float4* xr = reinterpret_cast<const float4*>(x + (size_t)row * K_DIM);
        float4 v[4];
        float amax = 0.f;
#pragma unroll
        for (int p = 0; p < 4; ++p) {
            v[p] = xr[p * 256 + t];
            amax = fmaxf(amax, fmaxf(fmaxf(fabsf(v[p].x), fabsf(v[p].y)),
                                     fmaxf(fabsf(v[p].z), fabsf(v[p].w))));
        }
#pragma unroll
        for (int o = 16; o; o >>= 1)
            amax = fmaxf(amax, __shfl_xor_sync(0xFFFFFFFFu, amax, o));

        __shared__ float smax[8];
        if ((t & 31) == 0) smax[t >> 5] = amax;
        __syncthreads();
        float bmax = fmaxf(fmaxf(fmaxf(smax[0], smax[1]), fmaxf(smax[2], smax[3])),
                           fmaxf(fmaxf(smax[4], smax[5]), fmaxf(smax[6], smax[7])));

        const float inv = (bmax > 0.f) ? (32639.f / bmax) : 0.f;
        if (t == 0) g_scale[row] = (bmax > 0.f) ? (bmax / 32639.f) : 0.f;

        char4* hp = reinterpret_cast<char4*>(g_xh8 + (size_t)row * K_DIM);
        char4* lp = reinterpret_cast<char4*>(g_xl8 + (size_t)row * K_DIM);
#pragma unroll
        for (int p = 0; p < 4; ++p) {
            int q0 = __float2int_rn(v[p].x * inv);
            int q1 = __float2int_rn(v[p].y * inv);
            int q2 = __float2int_rn(v[p].z * inv);
            int q3 = __float2int_rn(v[p].w * inv);
            int h0 = (q0 + 128) >> 8, h1 = (q1 + 128) >> 8;
            int h2 = (q2 + 128) >> 8, h3 = (q3 + 128) >> 8;
            char4 hc = make_char4((char)h0, (char)h1, (char)h2, (char)h3);
            char4 lc = make_char4((char)(q0 - (h0 << 8)), (char)(q1 - (h1 << 8)),
                                  (char)(q2 - (h2 << 8)), (char)(q3 - (h3 << 8)));
            hp[p * 256 + t] = hc;
            lp[p * 256 + t] = lc;
        }
    } else {
        size_t i = (size_t)(blockIdx.x - M_DIM) * 256 + t;   // float4 index
        float4 v = reinterpret_cast<const float4*>(w)[i];
        char4 c = make_char4((char)__float2int_rn(v.x), (char)__float2int_rn(v.y),
                             (char)__float2int_rn(v.z), (char)__float2int_rn(v.w));
        reinterpret_cast<char4*>(g_w8)[i] = c;
    }
}

// ---------------------------------------------------------------------------
// Main hybrid GEMM. CTA 64x128, 256 thr = 8 warps.
//   hi: warps 2m x 4n, warp tile 32x32, IMMA (accH[2][4][4]).
//   lo: per-thread 8x4 tile via dp4a; warp wid owns rows {wid+8i}, lane owns
//       cols {lane+32j}; a-loads are warp-uniform (broadcast).
// 4-stage cp.async ring, stage = [A_hi 8K][A_lo 8K][B 16K], SW128-xor swizzle.
// ---------------------------------------------------------------------------
__global__ void __launch_bounds__(256, 1)
gemm_s8_kernel(const float* __restrict__ bias, float* __restrict__ out) {
    extern __shared__ char smem[];
    const uint32_t sb = smem_u32(smem);
    const int tid = threadIdx.x;
    const int lane = tid & 31;
    const int wid = tid >> 5;
    const int wm = wid >> 2;           // 0..1
    const int wn = wid & 3;            // 0..3
    const int m0 = blockIdx.y * BM;
    const int n0 = blockIdx.x * BN;

    // --- cp.async mapping (8 x 16B chunks per thread = 32 KB/stage) ---
    const int arow = tid >> 2;
    const int acol = (tid & 3) * 2;
    const int8_t* gH = g_xh8 + (size_t)(m0 + arow) * K_DIM + acol * 16;
    const int8_t* gL = g_xl8 + (size_t)(m0 + arow) * K_DIM + acol * 16;
    const uint32_t aBase = (uint32_t)arow * BK;
    const uint32_t asw0 = aBase + (uint32_t)(((acol + 0) ^ (arow & 7)) << 4);
    const uint32_t asw1 = aBase + (uint32_t)(((acol + 1) ^ (arow & 7)) << 4);
    const int brow = tid >> 1;
    const int bcol = (tid & 1) * 4;
    const int8_t* gW = g_w8 + (size_t)(n0 + brow) * K_DIM + bcol * 16;
    const uint32_t bBase = B_OFF + (uint32_t)brow * BK;
    uint32_t bsw[4];
#pragma unroll
    for (int j = 0; j < 4; ++j)
        bsw[j] = bBase + (uint32_t)(((bcol + j) ^ (brow & 7)) << 4);

#define PREFETCH(it) do {                                                     \
    const int _k = (it) * BK;                                                 \
    const uint32_t _s = sb + (uint32_t)((it) & (NSTAGE - 1)) * STAGE_BYTES;   \
    CP16(_s + A_HI_OFF + asw0, gH + _k);                                      \
    CP16(_s + A_HI_OFF + asw1, gH + _k + 16);                                 \
    CP16(_s + A_LO_OFF + asw0, gL + _k);                                      \
    CP16(_s + A_LO_OFF + asw1, gL + _k + 16);                                 \
    CP16(_s + bsw[0], gW + _k);                                               \
    CP16(_s + bsw[1], gW + _k + 16);                                          \
    CP16(_s + bsw[2], gW + _k + 32);                                          \
    CP16(_s + bsw[3], gW + _k + 48);                                          \
} while (0)

    // --- hi-path ldmatrix lane addressing ---
    const int ag = lane >> 3;
    const int aRow0 = wm * 32 + ((ag & 1) << 3) + (lane & 7);
    const int agc = ag >> 1;
    const int bRow = wn * 32 + lane;
    const uint32_t bRowOff = B_OFF + (uint32_t)bRow * BK;
    const int bRowSw = bRow & 7;

    int accH[2][4][4];
#pragma unroll
    for (int mt = 0; mt < 2; ++mt)
#pragma unroll
        for (int nt = 0; nt < 4; ++nt)
#pragma unroll
            for (int i = 0; i < 4; ++i) accH[mt][nt][i] = 0;

    // --- lo-path setup: rows wid+8i (warp-uniform), cols lane+32j ---
    int accLo[8][4];
#pragma unroll
    for (int i = 0; i < 8; ++i)
#pragma unroll
        for (int j = 0; j < 4; ++j) accLo[i][j] = 0;
    const uint32_t loASw = (uint32_t)(wid & 7);             // row&7, warp-uniform
    uint32_t loBOff[4];
#pragma unroll
    for (int j = 0; j < 4; ++j)
        loBOff[j] = B_OFF + (uint32_t)(lane + 32 * j) * BK;
    const uint32_t loBSw = (uint32_t)(lane & 7);

    // --- prologue: fill 3 stages ---
    PREFETCH(0); CP_COMMIT();
    PREFETCH(1); CP_COMMIT();
    PREFETCH(2); CP_COMMIT();

    for (int it = 0; it < NKT; ++it) {
        CP_WAIT2();
        __syncthreads();
        if (it + 3 < NKT) { PREFETCH(it + 3); }
        CP_COMMIT();

        const uint32_t S = sb + (uint32_t)(it & (NSTAGE - 1)) * STAGE_BYTES;

        auto hi_pass = [&]() {
#pragma unroll
            for (int ks = 0; ks < 4; ++ks) {
                uint32_t b0[4], b1[4];
                uint32_t a0 = S + bRowOff + (uint32_t)(((ks * 2)     ^ bRowSw) << 4);
                uint32_t a1 = S + bRowOff + (uint32_t)(((ks * 2 + 1) ^ bRowSw) << 4);
                LDSM4(b0[0], b0[1], b0[2], b0[3], a0);
                LDSM4(b1[0], b1[1], b1[2], b1[3], a1);
                uint32_t ah[2][4];
#pragma unroll
                for (int mt = 0; mt < 2; ++mt) {
                    const int rA = aRow0 + mt * 16;
                    const int cA = ks * 2 + agc;
                    const uint32_t off = (uint32_t)rA * BK +
                                         (uint32_t)((cA ^ (rA & 7)) << 4);
                    LDSM4(ah[mt][0], ah[mt][1], ah[mt][2], ah[mt][3],
                          S + A_HI_OFF + off);
                }
#pragma unroll
                for (int mt = 0; mt < 2; ++mt)
#pragma unroll
                    for (int nt = 0; nt < 4; ++nt)
                        mma_s8(accH[mt][nt], ah[mt], b0[nt], b1[nt]);
            }
        };

        auto lo_pass = [&]() {
#pragma unroll 1
            for (int kc = 0; kc < 8; ++kc) {
                uint4 bw[4];
#pragma unroll
                for (int j = 0; j < 4; ++j)
                    bw[j] = *reinterpret_cast<const uint4*>(
                        smem + (S - sb) + loBOff[j] + ((kc ^ loBSw) << 4));
                uint4 aw[8];
#pragma unroll
                for (int i = 0; i < 8; ++i)
                    aw[i] = *reinterpret_cast<const uint4*>(
                        smem + (S - sb) + A_LO_OFF +
                        (uint32_t)(wid + 8 * i) * BK + ((kc ^ loASw) << 4));
#pragma unroll
                for (int i = 0; i < 8; ++i)
#pragma unroll
                    for (int j = 0; j < 4; ++j) {
                        int acc = accLo[i][j];
                        acc = __dp4a((int)aw[i].x, (int)bw[j].x, acc);
                        acc = __dp4a((int)aw[i].y, (int)bw[j].y, acc);
                        acc = __dp4a((int)aw[i].z, (int)bw[j].z, acc);
                        acc = __dp4a((int)aw[i].w, (int)bw[j].w, acc);
                        accLo[i][j] = acc;
                    }
            }
        };

        // Stagger pipe order: SMSP k hosts warps k (hi-first) and k+4
        // (lo-first) -> tensor and fma pipes overlap across the warp pair.
        if (wid < 4) { hi_pass(); lo_pass(); }
        else         { lo_pass(); hi_pass(); }

        __syncthreads();
    }

    // --- stage lo accumulators to smem (64 x 128 int32 = 32 KB) ---
    int* loS = reinterpret_cast<int*>(smem);
#pragma unroll
    for (int i = 0; i < 8; ++i)
#pragma unroll
        for (int j = 0; j < 4; ++j)
            loS[(wid + 8 * i) * BN + lane + 32 * j] = accLo[i][j];
    __syncthreads();

    // --- epilogue: combine hi/lo, scale, bias, store fp32 ---
#pragma unroll
    for (int mt = 0; mt < 2; ++mt) {
        const int rl = wm * 32 + mt * 16 + (lane >> 2);
        const int r0 = m0 + rl;
        const float s0 = g_scale[r0];
        const float s1 = g_scale[r0 + 8];
#pragma unroll
        for (int nt = 0; nt < 4; ++nt) {
            const int cl = wn * 32 + nt * 8 + 2 * (lane & 3);
            const int col = n0 + cl;
            const float bv0 = __ldg(bias + col);
            const float bv1 = __ldg(bias + col + 1);
            const int* h = accH[mt][nt];
            float2 o0, o1;
            o0.x = s0 * (float)(256 * h[0] + loS[rl * BN + cl])       + bv0;
            o0.y = s0 * (float)(256 * h[1] + loS[rl * BN + cl + 1])   + bv1;
            o1.x = s1 * (float)(256 * h[2] + loS[(rl + 8) * BN + cl])     + bv0;
            o1.y = s1 * (float)(256 * h[3] + loS[(rl + 8) * BN + cl + 1]) + bv1;
            *reinterpret_cast<float2*>(out + (size_t)r0 * N_DIM + col) = o0;
            *reinterpret_cast<float2*>(out + (size_t)(r0 + 8) * N_DIM + col) = o1;
        }
    }
#undef PREFETCH
}

// ---------------------------------------------------------------------------
// Launch
// ---------------------------------------------------------------------------
extern "C" void kernel_launch(void* const* d_in, const int* in_sizes, int n_in,
                              void* d_out, int out_size) {
    const float* x    = (const float*)d_in[0];
    const float* w    = (const float*)d_in[1];
    const float* bias = (const float*)d_in[2];
    float* out = (float*)d_out;

    quant_all_kernel<<<M_DIM + (N_DIM * K_DIM / 4) / 256, 256>>>(x, w);

    cudaFuncSetAttribute(gemm_s8_kernel,
                         cudaFuncAttributeMaxDynamicSharedMemorySize, SMEM_TOTAL);
    dim3 grid(N_DIM / BN, M_DIM / BM);   // (32, 128): n fastest -> W L2-resident
    gemm_s8_kernel<<<grid, 256, SMEM_TOTAL>>>(bias, out);
}